// round 15
// baseline (speedup 1.0000x reference)
#include <cuda_runtime.h>
#include <cuda_fp16.h>
#include <math.h>
#include <stdint.h>

#define NBATCH 2
#define OD 8
#define OH 28
#define OW 28
#define S_OUT 6272
#define NS 12544

__device__ __half g_cols[43352064];  // [ns][K], max K=3456
__device__ __half g_wh[6262272];     // all four weight sets, half
__device__ __half g_xh[6422528];     // x as half (NCDHW)
__device__ __half g_act[1605632];    // relu(bn1(out1)) as half, [c][NS]
__device__ float g_off1[8128512];    // [648][NS]
__device__ float g_off2[16257024];   // [1296][NS]
__device__ float g_out1[1605632];    // [128][NS]  (raw, pre-BN)
__device__ float g_out2[1605632];
__device__ float g_res[802816];      // [64][NS]
__device__ float g_mean[128];
__device__ float g_istd[128];

#define WH_OFF1 0
#define WH_CV1  1119744
#define WH_OFF2 1340928
#define WH_CV2  5819904
#define N_OFF1W 1119744
#define N_CV1W  221184
#define N_OFF2W 4478976
#define N_CV2W  442368

__device__ __forceinline__ uint32_t h2_as_u32(__half2 h) {
    return *(uint32_t*)&h;
}

// ---------------- all four weight sets fp32 -> fp16, one launch ----------------
__global__ void f2h_all(const float* __restrict__ w0, const float* __restrict__ w1,
                        const float* __restrict__ w2, const float* __restrict__ w3,
                        __half* __restrict__ out) {
    const int n40 = N_OFF1W / 4, n41 = N_CV1W / 4, n42 = N_OFF2W / 4, n43 = N_CV2W / 4;
    int i = blockIdx.x * blockDim.x + threadIdx.x;
    const float* src;
    int li;
    __half* dst;
    if (i < n40)                { src = w0; li = i;               dst = out + WH_OFF1; }
    else if (i < n40+n41)       { src = w1; li = i - n40;         dst = out + WH_CV1; }
    else if (i < n40+n41+n42)   { src = w2; li = i - n40-n41;     dst = out + WH_OFF2; }
    else if (i < n40+n41+n42+n43){ src = w3; li = i - n40-n41-n42; dst = out + WH_CV2; }
    else return;
    float4 v = ((const float4*)src)[li];
    __half2 h0 = __floats2half2_rn(v.x, v.y);
    __half2 h1 = __floats2half2_rn(v.z, v.w);
    ((uint2*)dst)[li] = make_uint2(h2_as_u32(h0), h2_as_u32(h1));
}

// ---------------- fp32 -> fp16, vectorized x4 ----------------
__global__ void f2h4_kernel(const float* __restrict__ in, __half* __restrict__ out, int n4) {
    int i = blockIdx.x * blockDim.x + threadIdx.x;
    if (i >= n4) return;
    float4 v = ((const float4*)in)[i];
    __half2 h0 = __floats2half2_rn(v.x, v.y);
    __half2 h1 = __floats2half2_rn(v.z, v.w);
    ((uint2*)out)[i] = make_uint2(h2_as_u32(h0), h2_as_u32(h1));
}

// ---------------- BN+relu -> fp16 act, vectorized x4 ----------------
__global__ void bn_act_h(const float* __restrict__ in, __half* __restrict__ out,
                         const float* __restrict__ gam, const float* __restrict__ bet,
                         const float* __restrict__ mean, const float* __restrict__ istd) {
    int i = blockIdx.x * blockDim.x + threadIdx.x;
    if (i >= 128 * NS / 4) return;
    int c = (i * 4) / NS;
    float sc = gam[c] * istd[c];
    float sh = bet[c] - mean[c] * sc;
    float4 v = ((const float4*)in)[i];
    v.x = fmaxf(sc * v.x + sh, 0.f);
    v.y = fmaxf(sc * v.y + sh, 0.f);
    v.z = fmaxf(sc * v.z + sh, 0.f);
    v.w = fmaxf(sc * v.w + sh, 0.f);
    __half2 h0 = __floats2half2_rn(v.x, v.y);
    __half2 h1 = __floats2half2_rn(v.z, v.w);
    ((uint2*)out)[i] = make_uint2(h2_as_u32(h0), h2_as_u32(h1));
}

// ---------------- maxpool (fp32 x -> fp32 residual, exact path) ----------------
__global__ void maxpool_kernel(const float* __restrict__ x, float* __restrict__ res) {
    int i = blockIdx.x * blockDim.x + threadIdx.x;
    if (i >= 64 * NS) return;
    int ns = i % NS, c = i / NS;
    int n = ns / S_OUT, s = ns % S_OUT;
    int od = s / (OH * OW), oh = (s / OW) % OH, ow = s % OW;
    const float* xp = x + ((size_t)(n * 64 + c)) * 16 * 56 * 56;
    int d0 = od * 2 - 1, h0 = oh * 2 - 1, w0 = ow * 2 - 1;
    int dlo = d0 < 0 ? 0 : d0, dhi = d0 + 2 > 15 ? 15 : d0 + 2;
    int hlo = h0 < 0 ? 0 : h0, hhi = h0 + 2 > 55 ? 55 : h0 + 2;
    int wlo = w0 < 0 ? 0 : w0, whi = w0 + 2 > 55 ? 55 : w0 + 2;
    float m = -INFINITY;
    for (int dd = dlo; dd <= dhi; dd++)
        for (int hh = hlo; hh <= hhi; hh++)
            for (int ww = wlo; ww <= whi; ww++)
                m = fmaxf(m, xp[(dd * 56 + hh) * 56 + ww]);
    res[(size_t)c * NS + ns] = m;
}

// ---------------------------------------------------------------------------
// Block-staged im2col (fp16 input) -> cols[ns][K] (half).
// ---------------------------------------------------------------------------
template <int C, int STRIDE, int NCDHW>
__global__ __launch_bounds__(864) void im2col_blk(
    const __half* __restrict__ in, __half* __restrict__ cols,
    int Din, int Hin, int Win) {
    __shared__ float sbuf[216 * 33];
    const int K = C * 27;
    int tid = threadIdx.x;
    int nsl = tid & 31, tap = tid >> 5;
    int nsb = blockIdx.x * 32, g = blockIdx.y;
    int ns = nsb + nsl;
    int n = ns / S_OUT, s = ns % S_OUT;
    int od = s / (OH * OW), oh = (s / OW) % OH, ow = s % OW;
    int kd = tap / 9, kh = (tap / 3) % 3, kw = tap % 3;
    int id = od * STRIDE - 1 + kd, ih = oh * STRIDE - 1 + kh, iw = ow * STRIDE - 1 + kw;
    bool valid = id >= 0 && id < Din && ih >= 0 && ih < Hin && iw >= 0 && iw < Win;
    int Sin = Din * Hin * Win;
    int sidx = valid ? (id * Hin + ih) * Win + iw : 0;

#pragma unroll
    for (int cc = 0; cc < 8; cc++) {
        int c = g * 8 + cc;
        size_t base = NCDHW ? ((size_t)(n * C + c)) * Sin : ((size_t)c * NBATCH + n) * Sin;
        float v = valid ? __half2float(in[base + sidx]) : 0.f;
        sbuf[(cc * 27 + tap) * 33 + nsl] = v;
    }
    __syncthreads();
#pragma unroll
    for (int it = 0; it < 2; it++) {
        int j = it * 864 + tid;
        int nsi = j / 54, kq = j % 54;
        __half2 h0 = __floats2half2_rn(sbuf[(kq * 4 + 0) * 33 + nsi],
                                       sbuf[(kq * 4 + 1) * 33 + nsi]);
        __half2 h1 = __floats2half2_rn(sbuf[(kq * 4 + 2) * 33 + nsi],
                                       sbuf[(kq * 4 + 3) * 33 + nsi]);
        *(uint2*)&cols[(size_t)(nsb + nsi) * K + g * 216 + kq * 4] =
            make_uint2(h2_as_u32(h0), h2_as_u32(h1));
    }
}

// ---------------------------------------------------------------------------
// Deformable im2col (fp16 input) -> cols[ns][K] (half), smem staged.
// ---------------------------------------------------------------------------
__global__ __launch_bounds__(864) void deform_T(
    const __half* __restrict__ in, const float* __restrict__ off,
    __half* __restrict__ cols, int C, int G, int Din, int Hin, int Win,
    int stride, int ncdhw) {
    __shared__ float sbuf[216 * 33];
    int K = C * 27;
    int tid = threadIdx.x;
    int nsl = tid & 31, tap = tid >> 5;
    int nsb = blockIdx.x * 32, g = blockIdx.y;
    int ns = nsb + nsl;
    int n = ns / S_OUT, s = ns % S_OUT;
    int od = s / (OH * OW), oh = (s / OW) % OH, ow = s % OW;
    int kd = tap / 9, kh = (tap / 3) % 3, kw = tap % 3;

    size_t ob = ((size_t)(g * 3) * 27 + tap) * NS + ns;
    float pd = off[ob]                   + (float)(od * stride - 1 + kd);
    float ph = off[ob + (size_t)27 * NS] + (float)(oh * stride - 1 + kh);
    float pw = off[ob + (size_t)54 * NS] + (float)(ow * stride - 1 + kw);
    float d0f = floorf(pd), h0f = floorf(ph), w0f = floorf(pw);
    int d0 = (int)d0f, h0 = (int)h0f, w0 = (int)w0f;
    float fd = pd - d0f, fh = ph - h0f, fw = pw - w0f;

    float wt8[8]; int idx8[8];
    int Sin = Din * Hin * Win;
#pragma unroll
    for (int cr = 0; cr < 8; cr++) {
        int cd = cr >> 2, ch = (cr >> 1) & 1, cw = cr & 1;
        int di = d0 + cd, hi = h0 + ch, wi = w0 + cw;
        bool valid = (di >= 0) && (di < Din) && (hi >= 0) && (hi < Hin) &&
                     (wi >= 0) && (wi < Win);
        float wt = (cd ? fd : 1.f - fd) * (ch ? fh : 1.f - fh) * (cw ? fw : 1.f - fw);
        wt8[cr] = valid ? wt : 0.f;
        int dic = di < 0 ? 0 : (di > Din - 1 ? Din - 1 : di);
        int hic = hi < 0 ? 0 : (hi > Hin - 1 ? Hin - 1 : hi);
        int wic = wi < 0 ? 0 : (wi > Win - 1 ? Win - 1 : wi);
        idx8[cr] = (dic * Hin + hic) * Win + wic;
    }
#pragma unroll
    for (int cc = 0; cc < 8; cc++) {
        int c = g * 8 + cc;
        size_t base = ncdhw ? ((size_t)(n * C + c)) * Sin : ((size_t)c * NBATCH + n) * Sin;
        const __half* bp = in + base;
        float acc = 0.f;
#pragma unroll
        for (int cr = 0; cr < 8; cr++) acc += wt8[cr] * __half2float(bp[idx8[cr]]);
        sbuf[(cc * 27 + tap) * 33 + nsl] = acc;
    }
    __syncthreads();
#pragma unroll
    for (int it = 0; it < 2; it++) {
        int j = it * 864 + tid;
        int nsi = j / 54, kq = j % 54;
        __half2 h0 = __floats2half2_rn(sbuf[(kq * 4 + 0) * 33 + nsi],
                                       sbuf[(kq * 4 + 1) * 33 + nsi]);
        __half2 h1 = __floats2half2_rn(sbuf[(kq * 4 + 2) * 33 + nsi],
                                       sbuf[(kq * 4 + 3) * 33 + nsi]);
        *(uint2*)&cols[(size_t)(nsb + nsi) * K + g * 216 + kq * 4] =
            make_uint2(h2_as_u32(h0), h2_as_u32(h1));
    }
}

// ---------------------------------------------------------------------------
// FP16 mma.sync GEMM, 512 threads / 16 warps (2x8), ldmatrix, BK=64, GST=3.
// C[M][NS] = A[M][K]*B^T (+bias). BM=128, BN {128,256}; warp tile 64x(BN/8).
// ---------------------------------------------------------------------------
#define HBK 64
#define HPH 72
#define GST 3
#define GTH 512

__device__ __forceinline__ void cpasync16h(__half* dst, const __half* src, bool pred) {
    uint32_t d = (uint32_t)__cvta_generic_to_shared(dst);
    int sz = pred ? 16 : 0;
    asm volatile("cp.async.cg.shared.global [%0], [%1], 16, %2;\n"
                 :: "r"(d), "l"(src), "r"(sz));
}
__device__ __forceinline__ void mma_f16(float* c, uint32_t a0, uint32_t a1,
                                        uint32_t a2, uint32_t a3,
                                        uint32_t b0, uint32_t b1) {
    asm volatile(
        "mma.sync.aligned.m16n8k16.row.col.f32.f16.f16.f32 "
        "{%0,%1,%2,%3}, {%4,%5,%6,%7}, {%8,%9}, {%0,%1,%2,%3};\n"
        : "+f"(c[0]), "+f"(c[1]), "+f"(c[2]), "+f"(c[3])
        : "r"(a0), "r"(a1), "r"(a2), "r"(a3), "r"(b0), "r"(b1));
}
__device__ __forceinline__ void ldsm_x4(uint32_t* r, uint32_t addr) {
    asm volatile("ldmatrix.sync.aligned.m8n8.x4.shared.b16 {%0,%1,%2,%3}, [%4];"
                 : "=r"(r[0]), "=r"(r[1]), "=r"(r[2]), "=r"(r[3]) : "r"(addr));
}

template <int BN>
__global__ __launch_bounds__(GTH) void gemm_h(
    const __half* __restrict__ A, const __half* __restrict__ B,
    const float* __restrict__ bias, float* __restrict__ C, int M, int K) {
    constexpr int BM = 128;
    constexpr int WN = BN / 8;      // 32 or 16
    constexpr int NT = WN / 8;      // 4 or 2
    constexpr int NB2 = NT / 2;     // B ldsm.x4 per ks: 2 or 1
    constexpr int AH = BM * HPH;
    constexpr int BH = BN * HPH;
    constexpr int ASL = BM * HBK / 8 / GTH;   // 2
    constexpr int BSL = BN * HBK / 8 / GTH;   // 4 (BN=256) or 2

    extern __shared__ __half smh[];
    __half* Asm = smh;
    __half* Bsm = smh + GST * AH;

    int tid = threadIdx.x;
    int warp = tid >> 5, lane = tid & 31;
    int wm = warp >> 3, wn = warp & 7;     // 2 x 8 warps
    int rg = lane >> 2, cg = lane & 3;
    int row0 = blockIdx.x * BM;
    int col0 = blockIdx.y * BN;
    int T = K / HBK;

    // cp.async slot geometry: 8 chunks (16B) per 64-half row
    int am[ASL], akq[ASL]; bool aok[ASL];
    const __half* asrc[ASL];
#pragma unroll
    for (int u = 0; u < ASL; u++) {
        int slot = u * GTH + tid;
        am[u] = slot >> 3; akq[u] = slot & 7;
        int gm = row0 + am[u];
        aok[u] = gm < M;
        asrc[u] = A + (size_t)(aok[u] ? gm : 0) * K + akq[u] * 8;
    }
    int bn_[BSL], bkq[BSL];
    const __half* bsrc[BSL];
#pragma unroll
    for (int u = 0; u < BSL; u++) {
        int slot = u * GTH + tid;
        bn_[u] = slot >> 3; bkq[u] = slot & 7;
        bsrc[u] = B + (size_t)(col0 + bn_[u]) * K + bkq[u] * 8;
    }

    // ldmatrix per-thread byte offsets within a stage (ks adds 32B each)
    uint32_t aBase = (uint32_t)__cvta_generic_to_shared(Asm);
    uint32_t bBase = (uint32_t)__cvta_generic_to_shared(Bsm);
    uint32_t aOff[4];
#pragma unroll
    for (int i = 0; i < 4; i++) {
        int row = wm * 64 + i * 16 + (lane & 15);
        int col = (lane >> 4) << 3;
        aOff[i] = (uint32_t)((row * HPH + col) * 2);
    }
    uint32_t bOff[NB2];
#pragma unroll
    for (int p = 0; p < NB2; p++) {
        int row = wn * WN + p * 16 + (lane & 7) + ((lane & 16) ? 8 : 0);
        int col = (lane & 8) ? 8 : 0;
        bOff[p] = (uint32_t)((row * HPH + col) * 2);
    }

    float acc[4][NT][4];
#pragma unroll
    for (int i = 0; i < 4; i++)
#pragma unroll
        for (int j = 0; j < NT; j++)
#pragma unroll
            for (int r = 0; r < 4; r++) acc[i][j][r] = 0.f;

    // prologue: tiles 0..GST-2
#pragma unroll
    for (int t = 0; t < GST - 1; t++) {
#pragma unroll
        for (int u = 0; u < ASL; u++)
            cpasync16h(&Asm[t * AH + am[u] * HPH + akq[u] * 8], asrc[u] + t * HBK, aok[u]);
#pragma unroll
        for (int u = 0; u < BSL; u++)
            cpasync16h(&Bsm[t * BH + bn_[u] * HPH + bkq[u] * 8], bsrc[u] + t * HBK, true);
        asm volatile("cp.async.commit_group;\n");
    }

    for (int t = 0; t < T; t++) {
        asm volatile("cp.async.wait_group 1;\n");
        __syncthreads();
        int st = t % GST;
        uint32_t aS = aBase + (uint32_t)(st * AH * 2);
        uint32_t bS = bBase + (uint32_t)(st * BH * 2);

#pragma unroll
        for (int ks = 0; ks < 4; ks++) {
            uint32_t kadd = ks * 32;   // 16 halves = 32 bytes
            uint32_t af[4][4], bf[NB2][4];
#pragma unroll
            for (int i = 0; i < 4; i++) ldsm_x4(af[i], aS + aOff[i] + kadd);
#pragma unroll
            for (int p = 0; p < NB2; p++) ldsm_x4(bf[p], bS + bOff[p] + kadd);
#pragma unroll
            for (int i = 0; i < 4; i++)
#pragma unroll
                for (int p = 0; p < NB2; p++) {
                    mma_f16(acc[i][2 * p],     af[i][0], af[i][1], af[i][2], af[i][3],
                            bf[p][0], bf[p][1]);
                    mma_f16(acc[i][2 * p + 1], af[i][0], af[i][1], af[i][2], af[i][3],
                            bf[p][2], bf[p][3]);
                }
        }

        int tn = t + GST - 1;
        if (tn < T) {
            int sn = tn % GST;
            int k0 = tn * HBK;
#pragma unroll
            for (int u = 0; u < ASL; u++)
                cpasync16h(&Asm[sn * AH + am[u] * HPH + akq[u] * 8], asrc[u] + k0, aok[u]);
#pragma unroll
            for (int u = 0; u < BSL; u++)
                cpasync16h(&Bsm[sn * BH + bn_[u] * HPH + bkq[u] * 8], bsrc[u] + k0, true);
        }
        asm volatile("cp.async.commit_group;\n");
    }

    // epilogue
#pragma unroll
    for (int i = 0; i < 4; i++) {
        int gm0 = row0 + wm * 64 + i * 16 + rg;
        int gm1 = gm0 + 8;
        float bv0 = (bias && gm0 < M) ? bias[gm0] : 0.f;
        float bv1 = (bias && gm1 < M) ? bias[gm1] : 0.f;
#pragma unroll
        for (int j = 0; j < NT; j++) {
            int gc = col0 + wn * WN + j * 8 + 2 * cg;
            if (gm0 < M)
                *(float2*)&C[(size_t)gm0 * NS + gc] =
                    make_float2(acc[i][j][0] + bv0, acc[i][j][1] + bv0);
            if (gm1 < M)
                *(float2*)&C[(size_t)gm1 * NS + gc] =
                    make_float2(acc[i][j][2] + bv1, acc[i][j][3] + bv1);
        }
    }
}

#define SMEMH256 (GST * (128 * HPH + 256 * HPH) * 2)   // 165888
#define SMEMH128 (GST * (128 * HPH + 128 * HPH) * 2)   // 110592

// ---------------- BN stats / final ----------------
__global__ void bn_stats(const float* __restrict__ x, float* __restrict__ mean,
                         float* __restrict__ istd) {
    int c = blockIdx.x;
    const float* row = x + (size_t)c * NS;
    float s = 0.f, s2 = 0.f;
    for (int i = threadIdx.x; i < NS / 4; i += blockDim.x) {
        float4 v = ((const float4*)row)[i];
        s += v.x + v.y + v.z + v.w;
        s2 += v.x * v.x + v.y * v.y + v.z * v.z + v.w * v.w;
    }
    __shared__ float sh[256], sh2[256];
    sh[threadIdx.x] = s; sh2[threadIdx.x] = s2;
    __syncthreads();
    for (int st = 128; st > 0; st >>= 1) {
        if (threadIdx.x < st) {
            sh[threadIdx.x] += sh[threadIdx.x + st];
            sh2[threadIdx.x] += sh2[threadIdx.x + st];
        }
        __syncthreads();
    }
    if (threadIdx.x == 0) {
        float m = sh[0] / (float)NS;
        float var = sh2[0] / (float)NS - m * m;
        mean[c] = m;
        istd[c] = rsqrtf(var + 1e-5f);
    }
}

__global__ void final_kernel(const float* __restrict__ raw, const float* __restrict__ gam,
                             const float* __restrict__ bet, const float* __restrict__ mean,
                             const float* __restrict__ istd, const float* __restrict__ res,
                             float* __restrict__ out) {
    int i = blockIdx.x * blockDim.x + threadIdx.x;
    if (i >= 128 * NS) return;
    int n = i / (128 * S_OUT);
    int co = (i / S_OUT) % 128;
    int s = i % S_OUT;
    float v = (raw[(size_t)co * NS + n * S_OUT + s] - mean[co]) * istd[co] * gam[co] + bet[co];
    v += res[(size_t)(co & 63) * NS + n * S_OUT + s];
    out[i] = fmaxf(v, 0.f);
}

// ---------------- host ----------------
extern "C" void kernel_launch(void* const* d_in, const int* in_sizes, int n_in,
                              void* d_out, int out_size) {
    (void)in_sizes; (void)n_in; (void)out_size;
    const float* x       = (const float*)d_in[0];
    const float* off1_w  = (const float*)d_in[1];
    const float* off1_b  = (const float*)d_in[2];
    const float* conv1_w = (const float*)d_in[3];
    const float* bn1_g   = (const float*)d_in[4];
    const float* bn1_b   = (const float*)d_in[5];
    const float* off2_w  = (const float*)d_in[6];
    const float* off2_b  = (const float*)d_in[7];
    const float* conv2_w = (const float*)d_in[8];
    const float* bn2_g   = (const float*)d_in[9];
    const float* bn2_b   = (const float*)d_in[10];
    float* out = (float*)d_out;

    __half *cols, *wh, *xh, *act;
    float *off1, *off2, *out1, *out2, *res, *mean, *istd;
    cudaGetSymbolAddress((void**)&cols, g_cols);
    cudaGetSymbolAddress((void**)&wh,   g_wh);
    cudaGetSymbolAddress((void**)&xh,   g_xh);
    cudaGetSymbolAddress((void**)&act,  g_act);
    cudaGetSymbolAddress((void**)&off1, g_off1);
    cudaGetSymbolAddress((void**)&off2, g_off2);
    cudaGetSymbolAddress((void**)&out1, g_out1);
    cudaGetSymbolAddress((void**)&out2, g_out2);
    cudaGetSymbolAddress((void**)&res,  g_res);
    cudaGetSymbolAddress((void**)&mean, g_mean);
    cudaGetSymbolAddress((void**)&istd, g_istd);

    static int attr_done = 0;
    if (!attr_done) {
        cudaFuncSetAttribute(gemm_h<256>, cudaFuncAttributeMaxDynamicSharedMemorySize, SMEMH256);
        cudaFuncSetAttribute(gemm_h<128>, cudaFuncAttributeMaxDynamicSharedMemorySize, SMEMH128);
        attr_done = 1;
    }

    const int T = 256;
    const int n4all = (N_OFF1W + N_CV1W + N_OFF2W + N_CV2W) / 4;

    // launch 1: all weights -> half
    f2h_all<<<(n4all + T - 1) / T, T>>>(off1_w, conv1_w, off2_w, conv2_w, wh);
    // launch 2: x -> half
    f2h4_kernel<<<(6422528 / 4 + T - 1) / T, T>>>(x, xh, 6422528 / 4);
    // launch 3: im2col for off1
    im2col_blk<64, 2, 1><<<dim3(NS / 32, 8), 864>>>(xh, cols, 16, 56, 56);
    // launch 4 (profiled by ncu): off1 GEMM, M=648, K=1728
    gemm_h<256><<<dim3(6, NS / 256), GTH, SMEMH256>>>(wh + WH_OFF1, cols, off1_b, off1, 648, 1728);
    // launch 5: residual maxpool (independent)
    maxpool_kernel<<<(64 * NS + T - 1) / T, T>>>(x, res);

    // out1 = deform_conv3d(x, off1, stride=2): M=128, K=1728
    deform_T<<<dim3(NS / 32, 8), 864>>>(xh, off1, cols, 64, 8, 16, 56, 56, 2, 1);
    gemm_h<128><<<dim3(1, NS / 128), GTH, SMEMH128>>>(wh + WH_CV1, cols, nullptr, out1, 128, 1728);

    bn_stats<<<128, 256>>>(out1, mean, istd);
    bn_act_h<<<(128 * NS / 4 + T - 1) / T, T>>>(out1, act, bn1_g, bn1_b, mean, istd);

    // off2 = conv3d(act, stride=1): M=1296, K=3456
    im2col_blk<128, 1, 0><<<dim3(NS / 32, 16), 864>>>(act, cols, 8, 28, 28);
    gemm_h<256><<<dim3(11, NS / 256), GTH, SMEMH256>>>(wh + WH_OFF2, cols, off2_b, off2, 1296, 3456);

    // out2 = deform_conv3d(act, off2, stride=1): M=128, K=3456
    deform_T<<<dim3(NS / 32, 16), 864>>>(act, off2, cols, 128, 16, 8, 28, 28, 1, 0);
    gemm_h<128><<<dim3(1, NS / 128), GTH, SMEMH128>>>(wh + WH_CV2, cols, nullptr, out2, 128, 3456);

    bn_stats<<<128, 256>>>(out2, mean, istd);
    final_kernel<<<(128 * NS + T - 1) / T, T>>>(out2, bn2_g, bn2_b, mean, istd, res, out);
}

// round 17
// speedup vs baseline: 1.0463x; 1.0463x over previous
#include <cuda_runtime.h>
#include <cuda_fp16.h>
#include <math.h>
#include <stdint.h>

#define NBATCH 2
#define OD 8
#define OH 28
#define OW 28
#define S_OUT 6272
#define NS 12544

__device__ __half g_cols[43352064];  // [ns][K], max K=3456
__device__ __half g_wh[6262272];     // all four weight sets, half
__device__ __half g_xh[6422528];     // x as half (NCDHW)
__device__ __half g_act[1605632];    // relu(bn1(out1)) as half, [c][NS]
__device__ float g_off1[8128512];    // [648][NS]
__device__ float g_off2[16257024];   // [1296][NS]
__device__ float g_out1[1605632];    // [128][NS]  (raw, pre-BN)
__device__ float g_out2[1605632];
__device__ float g_res[802816];      // [64][NS]
__device__ float g_mean[128];
__device__ float g_istd[128];

#define WH_OFF1 0
#define WH_CV1  1119744
#define WH_OFF2 1340928
#define WH_CV2  5819904
#define N_OFF1W 1119744
#define N_CV1W  221184
#define N_OFF2W 4478976
#define N_CV2W  442368

__device__ __forceinline__ uint32_t h2_as_u32(__half2 h) {
    return *(uint32_t*)&h;
}

// ---------------- all four weight sets fp32 -> fp16, one launch ----------------
__global__ void f2h_all(const float* __restrict__ w0, const float* __restrict__ w1,
                        const float* __restrict__ w2, const float* __restrict__ w3,
                        __half* __restrict__ out) {
    const int n40 = N_OFF1W / 4, n41 = N_CV1W / 4, n42 = N_OFF2W / 4, n43 = N_CV2W / 4;
    int i = blockIdx.x * blockDim.x + threadIdx.x;
    const float* src;
    int li;
    __half* dst;
    if (i < n40)                { src = w0; li = i;               dst = out + WH_OFF1; }
    else if (i < n40+n41)       { src = w1; li = i - n40;         dst = out + WH_CV1; }
    else if (i < n40+n41+n42)   { src = w2; li = i - n40-n41;     dst = out + WH_OFF2; }
    else if (i < n40+n41+n42+n43){ src = w3; li = i - n40-n41-n42; dst = out + WH_CV2; }
    else return;
    float4 v = ((const float4*)src)[li];
    __half2 h0 = __floats2half2_rn(v.x, v.y);
    __half2 h1 = __floats2half2_rn(v.z, v.w);
    ((uint2*)dst)[li] = make_uint2(h2_as_u32(h0), h2_as_u32(h1));
}

// ---------------- fp32 -> fp16, vectorized x4 ----------------
__global__ void f2h4_kernel(const float* __restrict__ in, __half* __restrict__ out, int n4) {
    int i = blockIdx.x * blockDim.x + threadIdx.x;
    if (i >= n4) return;
    float4 v = ((const float4*)in)[i];
    __half2 h0 = __floats2half2_rn(v.x, v.y);
    __half2 h1 = __floats2half2_rn(v.z, v.w);
    ((uint2*)out)[i] = make_uint2(h2_as_u32(h0), h2_as_u32(h1));
}

// ---------------- zero fp32 buffer, vectorized x4 ----------------
__global__ void zero4_kernel(float* __restrict__ p, int n4) {
    int i = blockIdx.x * blockDim.x + threadIdx.x;
    if (i < n4) ((float4*)p)[i] = make_float4(0.f, 0.f, 0.f, 0.f);
}

// ---------------- BN+relu -> fp16 act, vectorized x4 ----------------
__global__ void bn_act_h(const float* __restrict__ in, __half* __restrict__ out,
                         const float* __restrict__ gam, const float* __restrict__ bet,
                         const float* __restrict__ mean, const float* __restrict__ istd) {
    int i = blockIdx.x * blockDim.x + threadIdx.x;
    if (i >= 128 * NS / 4) return;
    int c = (i * 4) / NS;
    float sc = gam[c] * istd[c];
    float sh = bet[c] - mean[c] * sc;
    float4 v = ((const float4*)in)[i];
    v.x = fmaxf(sc * v.x + sh, 0.f);
    v.y = fmaxf(sc * v.y + sh, 0.f);
    v.z = fmaxf(sc * v.z + sh, 0.f);
    v.w = fmaxf(sc * v.w + sh, 0.f);
    __half2 h0 = __floats2half2_rn(v.x, v.y);
    __half2 h1 = __floats2half2_rn(v.z, v.w);
    ((uint2*)out)[i] = make_uint2(h2_as_u32(h0), h2_as_u32(h1));
}

// ---------------- maxpool (fp32 x -> fp32 residual, exact path) ----------------
__global__ void maxpool_kernel(const float* __restrict__ x, float* __restrict__ res) {
    int i = blockIdx.x * blockDim.x + threadIdx.x;
    if (i >= 64 * NS) return;
    int ns = i % NS, c = i / NS;
    int n = ns / S_OUT, s = ns % S_OUT;
    int od = s / (OH * OW), oh = (s / OW) % OH, ow = s % OW;
    const float* xp = x + ((size_t)(n * 64 + c)) * 16 * 56 * 56;
    int d0 = od * 2 - 1, h0 = oh * 2 - 1, w0 = ow * 2 - 1;
    int dlo = d0 < 0 ? 0 : d0, dhi = d0 + 2 > 15 ? 15 : d0 + 2;
    int hlo = h0 < 0 ? 0 : h0, hhi = h0 + 2 > 55 ? 55 : h0 + 2;
    int wlo = w0 < 0 ? 0 : w0, whi = w0 + 2 > 55 ? 55 : w0 + 2;
    float m = -INFINITY;
    for (int dd = dlo; dd <= dhi; dd++)
        for (int hh = hlo; hh <= hhi; hh++)
            for (int ww = wlo; ww <= whi; ww++)
                m = fmaxf(m, xp[(dd * 56 + hh) * 56 + ww]);
    res[(size_t)c * NS + ns] = m;
}

// ---------------------------------------------------------------------------
// Block-staged im2col (fp16 input) -> cols[ns][K] (half).
// ---------------------------------------------------------------------------
template <int C, int STRIDE, int NCDHW>
__global__ __launch_bounds__(864) void im2col_blk(
    const __half* __restrict__ in, __half* __restrict__ cols,
    int Din, int Hin, int Win) {
    __shared__ float sbuf[216 * 33];
    const int K = C * 27;
    int tid = threadIdx.x;
    int nsl = tid & 31, tap = tid >> 5;
    int nsb = blockIdx.x * 32, g = blockIdx.y;
    int ns = nsb + nsl;
    int n = ns / S_OUT, s = ns % S_OUT;
    int od = s / (OH * OW), oh = (s / OW) % OH, ow = s % OW;
    int kd = tap / 9, kh = (tap / 3) % 3, kw = tap % 3;
    int id = od * STRIDE - 1 + kd, ih = oh * STRIDE - 1 + kh, iw = ow * STRIDE - 1 + kw;
    bool valid = id >= 0 && id < Din && ih >= 0 && ih < Hin && iw >= 0 && iw < Win;
    int Sin = Din * Hin * Win;
    int sidx = valid ? (id * Hin + ih) * Win + iw : 0;

#pragma unroll
    for (int cc = 0; cc < 8; cc++) {
        int c = g * 8 + cc;
        size_t base = NCDHW ? ((size_t)(n * C + c)) * Sin : ((size_t)c * NBATCH + n) * Sin;
        float v = valid ? __half2float(in[base + sidx]) : 0.f;
        sbuf[(cc * 27 + tap) * 33 + nsl] = v;
    }
    __syncthreads();
#pragma unroll
    for (int it = 0; it < 2; it++) {
        int j = it * 864 + tid;
        int nsi = j / 54, kq = j % 54;
        __half2 h0 = __floats2half2_rn(sbuf[(kq * 4 + 0) * 33 + nsi],
                                       sbuf[(kq * 4 + 1) * 33 + nsi]);
        __half2 h1 = __floats2half2_rn(sbuf[(kq * 4 + 2) * 33 + nsi],
                                       sbuf[(kq * 4 + 3) * 33 + nsi]);
        *(uint2*)&cols[(size_t)(nsb + nsi) * K + g * 216 + kq * 4] =
            make_uint2(h2_as_u32(h0), h2_as_u32(h1));
    }
}

// ---------------------------------------------------------------------------
// Deformable im2col (fp16 input) -> cols[ns][K] (half), smem staged.
// ---------------------------------------------------------------------------
__global__ __launch_bounds__(864) void deform_T(
    const __half* __restrict__ in, const float* __restrict__ off,
    __half* __restrict__ cols, int C, int G, int Din, int Hin, int Win,
    int stride, int ncdhw) {
    __shared__ float sbuf[216 * 33];
    int K = C * 27;
    int tid = threadIdx.x;
    int nsl = tid & 31, tap = tid >> 5;
    int nsb = blockIdx.x * 32, g = blockIdx.y;
    int ns = nsb + nsl;
    int n = ns / S_OUT, s = ns % S_OUT;
    int od = s / (OH * OW), oh = (s / OW) % OH, ow = s % OW;
    int kd = tap / 9, kh = (tap / 3) % 3, kw = tap % 3;

    size_t ob = ((size_t)(g * 3) * 27 + tap) * NS + ns;
    float pd = off[ob]                   + (float)(od * stride - 1 + kd);
    float ph = off[ob + (size_t)27 * NS] + (float)(oh * stride - 1 + kh);
    float pw = off[ob + (size_t)54 * NS] + (float)(ow * stride - 1 + kw);
    float d0f = floorf(pd), h0f = floorf(ph), w0f = floorf(pw);
    int d0 = (int)d0f, h0 = (int)h0f, w0 = (int)w0f;
    float fd = pd - d0f, fh = ph - h0f, fw = pw - w0f;

    float wt8[8]; int idx8[8];
    int Sin = Din * Hin * Win;
#pragma unroll
    for (int cr = 0; cr < 8; cr++) {
        int cd = cr >> 2, ch = (cr >> 1) & 1, cw = cr & 1;
        int di = d0 + cd, hi = h0 + ch, wi = w0 + cw;
        bool valid = (di >= 0) && (di < Din) && (hi >= 0) && (hi < Hin) &&
                     (wi >= 0) && (wi < Win);
        float wt = (cd ? fd : 1.f - fd) * (ch ? fh : 1.f - fh) * (cw ? fw : 1.f - fw);
        wt8[cr] = valid ? wt : 0.f;
        int dic = di < 0 ? 0 : (di > Din - 1 ? Din - 1 : di);
        int hic = hi < 0 ? 0 : (hi > Hin - 1 ? Hin - 1 : hi);
        int wic = wi < 0 ? 0 : (wi > Win - 1 ? Win - 1 : wi);
        idx8[cr] = (dic * Hin + hic) * Win + wic;
    }
#pragma unroll
    for (int cc = 0; cc < 8; cc++) {
        int c = g * 8 + cc;
        size_t base = ncdhw ? ((size_t)(n * C + c)) * Sin : ((size_t)c * NBATCH + n) * Sin;
        const __half* bp = in + base;
        float acc = 0.f;
#pragma unroll
        for (int cr = 0; cr < 8; cr++) acc += wt8[cr] * __half2float(bp[idx8[cr]]);
        sbuf[(cc * 27 + tap) * 33 + nsl] = acc;
    }
    __syncthreads();
#pragma unroll
    for (int it = 0; it < 2; it++) {
        int j = it * 864 + tid;
        int nsi = j / 54, kq = j % 54;
        __half2 h0 = __floats2half2_rn(sbuf[(kq * 4 + 0) * 33 + nsi],
                                       sbuf[(kq * 4 + 1) * 33 + nsi]);
        __half2 h1 = __floats2half2_rn(sbuf[(kq * 4 + 2) * 33 + nsi],
                                       sbuf[(kq * 4 + 3) * 33 + nsi]);
        *(uint2*)&cols[(size_t)(nsb + nsi) * K + g * 216 + kq * 4] =
            make_uint2(h2_as_u32(h0), h2_as_u32(h1));
    }
}

// ---------------------------------------------------------------------------
// FP16 mma.sync GEMM (R14 config: BK=32, GST=4), 512 threads / 16 warps (2x8),
// ldmatrix loads. Optional split-K via blockIdx.z with atomicAdd epilogue.
// ---------------------------------------------------------------------------
#define HBK 32
#define HPH 40
#define GST 4
#define GTH 512

__device__ __forceinline__ void cpasync16h(__half* dst, const __half* src, bool pred) {
    uint32_t d = (uint32_t)__cvta_generic_to_shared(dst);
    int sz = pred ? 16 : 0;
    asm volatile("cp.async.cg.shared.global [%0], [%1], 16, %2;\n"
                 :: "r"(d), "l"(src), "r"(sz));
}
__device__ __forceinline__ void mma_f16(float* c, uint32_t a0, uint32_t a1,
                                        uint32_t a2, uint32_t a3,
                                        uint32_t b0, uint32_t b1) {
    asm volatile(
        "mma.sync.aligned.m16n8k16.row.col.f32.f16.f16.f32 "
        "{%0,%1,%2,%3}, {%4,%5,%6,%7}, {%8,%9}, {%0,%1,%2,%3};\n"
        : "+f"(c[0]), "+f"(c[1]), "+f"(c[2]), "+f"(c[3])
        : "r"(a0), "r"(a1), "r"(a2), "r"(a3), "r"(b0), "r"(b1));
}
__device__ __forceinline__ void ldsm_x4(uint32_t* r, uint32_t addr) {
    asm volatile("ldmatrix.sync.aligned.m8n8.x4.shared.b16 {%0,%1,%2,%3}, [%4];"
                 : "=r"(r[0]), "=r"(r[1]), "=r"(r[2]), "=r"(r[3]) : "r"(addr));
}

template <int BN, int SPLITK>
__global__ __launch_bounds__(GTH) void gemm_h(
    const __half* __restrict__ A, const __half* __restrict__ B,
    const float* __restrict__ bias, float* __restrict__ C, int M, int K) {
    constexpr int BM = 128;
    constexpr int WN = BN / 8;      // 32 or 16
    constexpr int NT = WN / 8;      // 4 or 2
    constexpr int NB2 = NT / 2;     // 2 or 1
    constexpr int AH = BM * HPH;
    constexpr int BH = BN * HPH;
    constexpr int ASL = BM * HBK / 8 / GTH;   // 1
    constexpr int BSL = BN * HBK / 8 / GTH;   // 2 or 1

    extern __shared__ __half smh[];
    __half* Asm = smh;
    __half* Bsm = smh + GST * AH;

    int tid = threadIdx.x;
    int warp = tid >> 5, lane = tid & 31;
    int wm = warp >> 3, wn = warp & 7;
    int rg = lane >> 2, cg = lane & 3;
    int row0 = blockIdx.x * BM;
    int col0 = blockIdx.y * BN;
    int Kz = K / SPLITK;
    int kz0 = blockIdx.z * Kz;
    int T = Kz / HBK;

    int am[ASL], akq[ASL]; bool aok[ASL];
    const __half* asrc[ASL];
#pragma unroll
    for (int u = 0; u < ASL; u++) {
        int slot = u * GTH + tid;
        am[u] = slot >> 2; akq[u] = slot & 3;
        int gm = row0 + am[u];
        aok[u] = gm < M;
        asrc[u] = A + (size_t)(aok[u] ? gm : 0) * K + kz0 + akq[u] * 8;
    }
    int bn_[BSL], bkq[BSL];
    const __half* bsrc[BSL];
#pragma unroll
    for (int u = 0; u < BSL; u++) {
        int slot = u * GTH + tid;
        bn_[u] = slot >> 2; bkq[u] = slot & 3;
        bsrc[u] = B + (size_t)(col0 + bn_[u]) * K + kz0 + bkq[u] * 8;
    }

    uint32_t aBase = (uint32_t)__cvta_generic_to_shared(Asm);
    uint32_t bBase = (uint32_t)__cvta_generic_to_shared(Bsm);
    uint32_t aOff[4];
#pragma unroll
    for (int i = 0; i < 4; i++) {
        int row = wm * 64 + i * 16 + (lane & 15);
        int col = (lane >> 4) << 3;
        aOff[i] = (uint32_t)((row * HPH + col) * 2);
    }
    uint32_t bOff[NB2];
#pragma unroll
    for (int p = 0; p < NB2; p++) {
        int row = wn * WN + p * 16 + (lane & 7) + ((lane & 16) ? 8 : 0);
        int col = (lane & 8) ? 8 : 0;
        bOff[p] = (uint32_t)((row * HPH + col) * 2);
    }

    float acc[4][NT][4];
#pragma unroll
    for (int i = 0; i < 4; i++)
#pragma unroll
        for (int j = 0; j < NT; j++)
#pragma unroll
            for (int r = 0; r < 4; r++) acc[i][j][r] = 0.f;

#pragma unroll
    for (int t = 0; t < GST - 1; t++) {
#pragma unroll
        for (int u = 0; u < ASL; u++)
            cpasync16h(&Asm[t * AH + am[u] * HPH + akq[u] * 8], asrc[u] + t * HBK, aok[u]);
#pragma unroll
        for (int u = 0; u < BSL; u++)
            cpasync16h(&Bsm[t * BH + bn_[u] * HPH + bkq[u] * 8], bsrc[u] + t * HBK, true);
        asm volatile("cp.async.commit_group;\n");
    }

    for (int t = 0; t < T; t++) {
        asm volatile("cp.async.wait_group 2;\n");
        __syncthreads();
        int st = t % GST;
        uint32_t aS = aBase + (uint32_t)(st * AH * 2);
        uint32_t bS = bBase + (uint32_t)(st * BH * 2);

#pragma unroll
        for (int ks = 0; ks < 2; ks++) {
            uint32_t kadd = ks * 32;
            uint32_t af[4][4], bf[NB2][4];
#pragma unroll
            for (int i = 0; i < 4; i++) ldsm_x4(af[i], aS + aOff[i] + kadd);
#pragma unroll
            for (int p = 0; p < NB2; p++) ldsm_x4(bf[p], bS + bOff[p] + kadd);
#pragma unroll
            for (int i = 0; i < 4; i++)
#pragma unroll
                for (int p = 0; p < NB2; p++) {
                    mma_f16(acc[i][2 * p],     af[i][0], af[i][1], af[i][2], af[i][3],
                            bf[p][0], bf[p][1]);
                    mma_f16(acc[i][2 * p + 1], af[i][0], af[i][1], af[i][2], af[i][3],
                            bf[p][2], bf[p][3]);
                }
        }

        int tn = t + GST - 1;
        if (tn < T) {
            int sn = tn % GST;
            int k0 = tn * HBK;
#pragma unroll
            for (int u = 0; u < ASL; u++)
                cpasync16h(&Asm[sn * AH + am[u] * HPH + akq[u] * 8], asrc[u] + k0, aok[u]);
#pragma unroll
            for (int u = 0; u < BSL; u++)
                cpasync16h(&Bsm[sn * BH + bn_[u] * HPH + bkq[u] * 8], bsrc[u] + k0, true);
        }
        asm volatile("cp.async.commit_group;\n");
    }

    // epilogue
#pragma unroll
    for (int i = 0; i < 4; i++) {
        int gm0 = row0 + wm * 64 + i * 16 + rg;
        int gm1 = gm0 + 8;
        float bv0 = (bias && gm0 < M) ? bias[gm0] : 0.f;
        float bv1 = (bias && gm1 < M) ? bias[gm1] : 0.f;
#pragma unroll
        for (int j = 0; j < NT; j++) {
            int gc = col0 + wn * WN + j * 8 + 2 * cg;
            if (SPLITK > 1) {
                if (gm0 < M) {
                    atomicAdd(&C[(size_t)gm0 * NS + gc],     acc[i][j][0]);
                    atomicAdd(&C[(size_t)gm0 * NS + gc + 1], acc[i][j][1]);
                }
                if (gm1 < M) {
                    atomicAdd(&C[(size_t)gm1 * NS + gc],     acc[i][j][2]);
                    atomicAdd(&C[(size_t)gm1 * NS + gc + 1], acc[i][j][3]);
                }
            } else {
                if (gm0 < M)
                    *(float2*)&C[(size_t)gm0 * NS + gc] =
                        make_float2(acc[i][j][0] + bv0, acc[i][j][1] + bv0);
                if (gm1 < M)
                    *(float2*)&C[(size_t)gm1 * NS + gc] =
                        make_float2(acc[i][j][2] + bv1, acc[i][j][3] + bv1);
            }
        }
    }
}

#define SMEMH256 (GST * (128 * HPH + 256 * HPH) * 2)   // 122880
#define SMEMH128 (GST * (128 * HPH + 128 * HPH) * 2)   // 81920

// ---------------- BN stats / final ----------------
__global__ void bn_stats(const float* __restrict__ x, float* __restrict__ mean,
                         float* __restrict__ istd) {
    int c = blockIdx.x;
    const float* row = x + (size_t)c * NS;
    float s = 0.f, s2 = 0.f;
    for (int i = threadIdx.x; i < NS / 4; i += blockDim.x) {
        float4 v = ((const float4*)row)[i];
        s += v.x + v.y + v.z + v.w;
        s2 += v.x * v.x + v.y * v.y + v.z * v.z + v.w * v.w;
    }
    __shared__ float sh[256], sh2[256];
    sh[threadIdx.x] = s; sh2[threadIdx.x] = s2;
    __syncthreads();
    for (int st = 128; st > 0; st >>= 1) {
        if (threadIdx.x < st) {
            sh[threadIdx.x] += sh[threadIdx.x + st];
            sh2[threadIdx.x] += sh2[threadIdx.x + st];
        }
        __syncthreads();
    }
    if (threadIdx.x == 0) {
        float m = sh[0] / (float)NS;
        float var = sh2[0] / (float)NS - m * m;
        mean[c] = m;
        istd[c] = rsqrtf(var + 1e-5f);
    }
}

__global__ void final_kernel(const float* __restrict__ raw, const float* __restrict__ gam,
                             const float* __restrict__ bet, const float* __restrict__ mean,
                             const float* __restrict__ istd, const float* __restrict__ res,
                             float* __restrict__ out) {
    int i = blockIdx.x * blockDim.x + threadIdx.x;
    if (i >= 128 * NS) return;
    int n = i / (128 * S_OUT);
    int co = (i / S_OUT) % 128;
    int s = i % S_OUT;
    float v = (raw[(size_t)co * NS + n * S_OUT + s] - mean[co]) * istd[co] * gam[co] + bet[co];
    v += res[(size_t)(co & 63) * NS + n * S_OUT + s];
    out[i] = fmaxf(v, 0.f);
}

// ---------------- host ----------------
extern "C" void kernel_launch(void* const* d_in, const int* in_sizes, int n_in,
                              void* d_out, int out_size) {
    (void)in_sizes; (void)n_in; (void)out_size;
    const float* x       = (const float*)d_in[0];
    const float* off1_w  = (const float*)d_in[1];
    const float* off1_b  = (const float*)d_in[2];
    const float* conv1_w = (const float*)d_in[3];
    const float* bn1_g   = (const float*)d_in[4];
    const float* bn1_b   = (const float*)d_in[5];
    const float* off2_w  = (const float*)d_in[6];
    const float* off2_b  = (const float*)d_in[7];
    const float* conv2_w = (const float*)d_in[8];
    const float* bn2_g   = (const float*)d_in[9];
    const float* bn2_b   = (const float*)d_in[10];
    float* out = (float*)d_out;

    __half *cols, *wh, *xh, *act;
    float *off1, *off2, *out1, *out2, *res, *mean, *istd;
    cudaGetSymbolAddress((void**)&cols, g_cols);
    cudaGetSymbolAddress((void**)&wh,   g_wh);
    cudaGetSymbolAddress((void**)&xh,   g_xh);
    cudaGetSymbolAddress((void**)&act,  g_act);
    cudaGetSymbolAddress((void**)&off1, g_off1);
    cudaGetSymbolAddress((void**)&off2, g_off2);
    cudaGetSymbolAddress((void**)&out1, g_out1);
    cudaGetSymbolAddress((void**)&out2, g_out2);
    cudaGetSymbolAddress((void**)&res,  g_res);
    cudaGetSymbolAddress((void**)&mean, g_mean);
    cudaGetSymbolAddress((void**)&istd, g_istd);

    static int attr_done = 0;
    if (!attr_done) {
        cudaFuncSetAttribute((const void*)gemm_h<256, 1>,
                             cudaFuncAttributeMaxDynamicSharedMemorySize, SMEMH256);
        cudaFuncSetAttribute((const void*)gemm_h<128, 3>,
                             cudaFuncAttributeMaxDynamicSharedMemorySize, SMEMH128);
        attr_done = 1;
    }

    const int T = 256;
    const int n4all = (N_OFF1W + N_CV1W + N_OFF2W + N_CV2W) / 4;

    // launch 1: all weights -> half
    f2h_all<<<(n4all + T - 1) / T, T>>>(off1_w, conv1_w, off2_w, conv2_w, wh);
    // launch 2: x -> half
    f2h4_kernel<<<(6422528 / 4 + T - 1) / T, T>>>(x, xh, 6422528 / 4);
    // launch 3: im2col for off1
    im2col_blk<64, 2, 1><<<dim3(NS / 32, 8), 864>>>(xh, cols, 16, 56, 56);
    // launch 4 (profiled by ncu): off1 GEMM, M=648, K=1728
    gemm_h<256, 1><<<dim3(6, NS / 256), GTH, SMEMH256>>>(wh + WH_OFF1, cols, off1_b, off1, 648, 1728);
    // independent housework: residual maxpool + zero split-K accumulators
    maxpool_kernel<<<(64 * NS + T - 1) / T, T>>>(x, res);
    zero4_kernel<<<(128 * NS / 4 + T - 1) / T, T>>>(out1, 128 * NS / 4);
    zero4_kernel<<<(128 * NS / 4 + T - 1) / T, T>>>(out2, 128 * NS / 4);

    // out1 = deform_conv3d(x, off1, stride=2): M=128, K=1728, split-K=3
    deform_T<<<dim3(NS / 32, 8), 864>>>(xh, off1, cols, 64, 8, 16, 56, 56, 2, 1);
    gemm_h<128, 3><<<dim3(1, NS / 128, 3), GTH, SMEMH128>>>(wh + WH_CV1, cols, nullptr, out1, 128, 1728);

    bn_stats<<<128, 256>>>(out1, mean, istd);
    bn_act_h<<<(128 * NS / 4 + T - 1) / T, T>>>(out1, act, bn1_g, bn1_b, mean, istd);

    // off2 = conv3d(act, stride=1): M=1296, K=3456
    im2col_blk<128, 1, 0><<<dim3(NS / 32, 16), 864>>>(act, cols, 8, 28, 28);
    gemm_h<256, 1><<<dim3(11, NS / 256), GTH, SMEMH256>>>(wh + WH_OFF2, cols, off2_b, off2, 1296, 3456);

    // out2 = deform_conv3d(act, off2, stride=1): M=128, K=3456, split-K=3
    deform_T<<<dim3(NS / 32, 16), 864>>>(act, off2, cols, 128, 16, 8, 28, 28, 1, 0);
    gemm_h<128, 3><<<dim3(1, NS / 128, 3), GTH, SMEMH128>>>(wh + WH_CV2, cols, nullptr, out2, 128, 3456);

    bn_stats<<<128, 256>>>(out2, mean, istd);
    final_kernel<<<(128 * NS + T - 1) / T, T>>>(out2, bn2_g, bn2_b, mean, istd, res, out);
}